// round 1
// baseline (speedup 1.0000x reference)
#include <cuda_runtime.h>

// ---------------------------------------------------------------------------
// AttnBlock: LN(channel) -> q(1x1), k(3x3), v(3x3) -> spatial attention ->
// 1x1 proj + bias -> residual.  B=4, C=512, H=W=64 (HW=4096), fp32.
// ---------------------------------------------------------------------------

namespace {
constexpr int CH   = 512;
constexpr int NB   = 4;
constexpr int HWs  = 4096;   // 64*64
constexpr int PWs  = 66;     // padded width
constexpr int PHWs = PWs * PWs; // 4356
}

// ------------------------- scratch (device globals) ------------------------
__device__ float g_mu [NB * HWs];
__device__ float g_rs [NB * HWs];
__device__ float g_mx [NB * HWs];
__device__ float g_si [NB * HWs];
__device__ float g_hp [(size_t)NB * CH * PHWs];     // padded LN output
__device__ float g_q  [(size_t)NB * CH * HWs];
__device__ float g_k  [(size_t)NB * CH * HWs];
__device__ float g_v  [(size_t)NB * CH * HWs];
__device__ float g_ao [(size_t)NB * CH * HWs];
__device__ float g_S  [(size_t)NB * HWs * HWs];     // 256 MB logits
__device__ float g_Pt [(size_t)NB * HWs * HWs];     // 256 MB transposed probs
__device__ float g_wkt[(size_t)9 * CH * CH];        // wk reorg [t][o][i]
__device__ float g_wvt[(size_t)9 * CH * CH];

// ------------------------------- utility -----------------------------------
__global__ void k_zero(float* __restrict__ p, size_t n) {
    size_t i = (size_t)blockIdx.x * blockDim.x + threadIdx.x;
    size_t stride = (size_t)gridDim.x * blockDim.x;
    for (; i < n; i += stride) p[i] = 0.f;
}

// reorg conv weight [O,I,3,3] -> [t][O][I]
__global__ void k_reorg(const float* __restrict__ w, float* __restrict__ wt) {
    int g = blockIdx.x * blockDim.x + threadIdx.x; // 0 .. CH*CH-1
    #pragma unroll
    for (int t = 0; t < 9; t++)
        wt[(size_t)t * CH * CH + g] = w[(size_t)g * 9 + t];
}

// ------------------------------ LayerNorm ----------------------------------
__global__ void k_ln_stats(const float* __restrict__ x) {
    int p = blockIdx.x * blockDim.x + threadIdx.x; // 0..HW-1
    int b = blockIdx.y;
    const float* xb = x + (size_t)b * CH * HWs + p;
    float s = 0.f, s2 = 0.f;
    #pragma unroll 8
    for (int c = 0; c < CH; c++) {
        float v = xb[(size_t)c * HWs];
        s += v; s2 += v * v;
    }
    float mu  = s * (1.f / CH);
    float var = s2 * (1.f / CH) - mu * mu;
    g_mu[b * HWs + p] = mu;
    g_rs[b * HWs + p] = rsqrtf(var + 1e-6f);
}

// writes LN result into padded buffer (interior); border stays zero.
__global__ void k_ln_apply(const float* __restrict__ x,
                           const float* __restrict__ lw,
                           const float* __restrict__ lb) {
    int p = blockIdx.x * blockDim.x + threadIdx.x;
    int c = blockIdx.y, b = blockIdx.z;
    float v = x[((size_t)b * CH + c) * HWs + p];
    float h = (v - g_mu[b * HWs + p]) * g_rs[b * HWs + p] * lw[c] + lb[c];
    g_hp[((size_t)b * CH + c) * PHWs + (size_t)((p >> 6) + 1) * PWs + (p & 63) + 1] = h;
}

// ------------------------ implicit-GEMM convolution -------------------------
// out[o, p] = sum_{t, i} Wt[t][o][i] * hp[i, spo(p) + tapoff(t)]
// T=1 => 1x1 conv (center tap), T=9 => 3x3 pad-1 conv.  M=512, N=4096.
__global__ __launch_bounds__(256)
void k_conv(const float* __restrict__ Wt, const float* __restrict__ hpb,
            float* __restrict__ Co, int T) {
    __shared__ float As[16][132];
    __shared__ float Bs[16][132];
    const int tid = threadIdx.x;
    const int tx = tid & 15, ty = tid >> 4;
    const int bn = blockIdx.x * 128, bm = blockIdx.y * 128;
    const float* hp = hpb + (size_t)blockIdx.z * CH * PHWs;
    float* C = Co + (size_t)blockIdx.z * CH * HWs;

    const int nG  = bn + (tid & 127);
    const int spo = ((nG >> 6) * PWs) + (nG & 63);
    const int kB  = tid >> 7;      // 0/1
    const int kA  = tid & 15;
    const int mA  = tid >> 4;      // 0..15

    float acc[8][8];
    #pragma unroll
    for (int i = 0; i < 8; i++)
        #pragma unroll
        for (int j = 0; j < 8; j++) acc[i][j] = 0.f;

    const int KT = T * CH;
    float ra[8], rb[8];

    // prefetch tile 0 (t = 0)
    {
        int off = (T == 9) ? 0 : (PWs + 1);
        #pragma unroll
        for (int j = 0; j < 8; j++)
            ra[j] = Wt[(size_t)(bm + mA + 16 * j) * CH + kA];
        #pragma unroll
        for (int j = 0; j < 8; j++)
            rb[j] = hp[(size_t)(kB + 2 * j) * PHWs + spo + off];
    }

    for (int kt0 = 0; kt0 < KT; kt0 += 16) {
        #pragma unroll
        for (int j = 0; j < 8; j++) As[kA][mA + 16 * j] = ra[j];
        #pragma unroll
        for (int j = 0; j < 8; j++) Bs[kB + 2 * j][tid & 127] = rb[j];
        __syncthreads();

        int nxt = kt0 + 16;
        if (nxt < KT) {
            int t = nxt >> 9, k0 = nxt & 511;
            const float* Ab = Wt + (size_t)t * CH * CH;
            int off = (T == 9) ? ((t / 3) * PWs + (t % 3)) : (PWs + 1);
            #pragma unroll
            for (int j = 0; j < 8; j++)
                ra[j] = Ab[(size_t)(bm + mA + 16 * j) * CH + k0 + kA];
            #pragma unroll
            for (int j = 0; j < 8; j++)
                rb[j] = hp[(size_t)(k0 + kB + 2 * j) * PHWs + spo + off];
        }

        #pragma unroll
        for (int kk = 0; kk < 16; kk++) {
            float4 a0 = *(const float4*)&As[kk][ty * 4];
            float4 a1 = *(const float4*)&As[kk][64 + ty * 4];
            float4 b0 = *(const float4*)&Bs[kk][tx * 4];
            float4 b1 = *(const float4*)&Bs[kk][64 + tx * 4];
            float av[8] = {a0.x,a0.y,a0.z,a0.w,a1.x,a1.y,a1.z,a1.w};
            float bw[8] = {b0.x,b0.y,b0.z,b0.w,b1.x,b1.y,b1.z,b1.w};
            #pragma unroll
            for (int i = 0; i < 8; i++)
                #pragma unroll
                for (int j = 0; j < 8; j++)
                    acc[i][j] = fmaf(av[i], bw[j], acc[i][j]);
        }
        __syncthreads();
    }

    const int n0 = bn + tx * 4;
    #pragma unroll
    for (int i = 0; i < 8; i++) {
        int m = bm + ty * 4 + (i & 3) + ((i >> 2) << 6);
        float4 o0 = {acc[i][0], acc[i][1], acc[i][2], acc[i][3]};
        float4 o1 = {acc[i][4], acc[i][5], acc[i][6], acc[i][7]};
        *(float4*)&C[(size_t)m * HWs + n0]      = o0;
        *(float4*)&C[(size_t)m * HWs + n0 + 64] = o1;
    }
}

// ------------------------------ tiled GEMM ----------------------------------
// C[m,n] = alpha * sum_k A(m,k) * B[k,n]  (+ bias[m]) (+ resid[m,n])
// TRANSA=false: A addr = m*lda + k ; TRANSA=true: A addr = k*lda + m.
// B row-major [K,N], ldb.  Batch via blockIdx.z with strides sA/sB/sC.
template <bool TRANSA>
__global__ __launch_bounds__(256)
void k_gemm(const float* __restrict__ A, const float* __restrict__ Bm,
            float* __restrict__ Co, int K, int lda, int ldb, int ldc,
            float alpha, const float* __restrict__ bias,
            const float* __restrict__ resid,
            size_t sA, size_t sB, size_t sC) {
    __shared__ float As[16][132];
    __shared__ float Bs[16][132];
    const int tid = threadIdx.x;
    const int tx = tid & 15, ty = tid >> 4;
    const int bn = blockIdx.x * 128, bm = blockIdx.y * 128;
    A  += (size_t)blockIdx.z * sA;
    Bm += (size_t)blockIdx.z * sB;
    Co += (size_t)blockIdx.z * sC;
    if (resid) resid += (size_t)blockIdx.z * sC;

    const int nL = tid & 127;
    const int kH = tid >> 7;
    const int kA = tid & 15;
    const int mA = tid >> 4;

    float acc[8][8];
    #pragma unroll
    for (int i = 0; i < 8; i++)
        #pragma unroll
        for (int j = 0; j < 8; j++) acc[i][j] = 0.f;

    float ra[8], rb[8];
    #pragma unroll
    for (int j = 0; j < 8; j++) {
        if (TRANSA) ra[j] = A[(size_t)(kH + 2 * j) * lda + bm + nL];
        else        ra[j] = A[(size_t)(bm + mA + 16 * j) * lda + kA];
        rb[j] = Bm[(size_t)(kH + 2 * j) * ldb + bn + nL];
    }

    for (int k0 = 0; k0 < K; k0 += 16) {
        #pragma unroll
        for (int j = 0; j < 8; j++) {
            if (TRANSA) As[kH + 2 * j][nL] = ra[j];
            else        As[kA][mA + 16 * j] = ra[j];
            Bs[kH + 2 * j][nL] = rb[j];
        }
        __syncthreads();

        if (k0 + 16 < K) {
            #pragma unroll
            for (int j = 0; j < 8; j++) {
                if (TRANSA) ra[j] = A[(size_t)(k0 + 16 + kH + 2 * j) * lda + bm + nL];
                else        ra[j] = A[(size_t)(bm + mA + 16 * j) * lda + k0 + 16 + kA];
                rb[j] = Bm[(size_t)(k0 + 16 + kH + 2 * j) * ldb + bn + nL];
            }
        }

        #pragma unroll
        for (int kk = 0; kk < 16; kk++) {
            float4 a0 = *(const float4*)&As[kk][ty * 4];
            float4 a1 = *(const float4*)&As[kk][64 + ty * 4];
            float4 b0 = *(const float4*)&Bs[kk][tx * 4];
            float4 b1 = *(const float4*)&Bs[kk][64 + tx * 4];
            float av[8] = {a0.x,a0.y,a0.z,a0.w,a1.x,a1.y,a1.z,a1.w};
            float bw[8] = {b0.x,b0.y,b0.z,b0.w,b1.x,b1.y,b1.z,b1.w};
            #pragma unroll
            for (int i = 0; i < 8; i++)
                #pragma unroll
                for (int j = 0; j < 8; j++)
                    acc[i][j] = fmaf(av[i], bw[j], acc[i][j]);
        }
        __syncthreads();
    }

    const int n0 = bn + tx * 4;
    #pragma unroll
    for (int i = 0; i < 8; i++) {
        const int m = bm + ty * 4 + (i & 3) + ((i >> 2) << 6);
        const float bv = bias ? bias[m] : 0.f;
        float4 o0, o1;
        o0.x = fmaf(acc[i][0], alpha, bv);
        o0.y = fmaf(acc[i][1], alpha, bv);
        o0.z = fmaf(acc[i][2], alpha, bv);
        o0.w = fmaf(acc[i][3], alpha, bv);
        o1.x = fmaf(acc[i][4], alpha, bv);
        o1.y = fmaf(acc[i][5], alpha, bv);
        o1.z = fmaf(acc[i][6], alpha, bv);
        o1.w = fmaf(acc[i][7], alpha, bv);
        if (resid) {
            float4 r0 = *(const float4*)&resid[(size_t)m * ldc + n0];
            float4 r1 = *(const float4*)&resid[(size_t)m * ldc + n0 + 64];
            o0.x += r0.x; o0.y += r0.y; o0.z += r0.z; o0.w += r0.w;
            o1.x += r1.x; o1.y += r1.y; o1.z += r1.z; o1.w += r1.w;
        }
        *(float4*)&Co[(size_t)m * ldc + n0]      = o0;
        *(float4*)&Co[(size_t)m * ldc + n0 + 64] = o1;
    }
}

// ------------------------------- softmax ------------------------------------
__global__ void k_softmax_stats(const float* __restrict__ S) {
    const int m = blockIdx.x, b = blockIdx.y;
    const float* row = S + ((size_t)b * HWs + m) * HWs;
    __shared__ float buf[HWs];
    __shared__ float red[256];
    const int tid = threadIdx.x;

    float lmax = -1e30f;
    for (int i = tid; i < HWs; i += 256) {
        float v = row[i];
        buf[i] = v;
        lmax = fmaxf(lmax, v);
    }
    red[tid] = lmax;
    __syncthreads();
    #pragma unroll
    for (int s = 128; s > 0; s >>= 1) {
        if (tid < s) red[tid] = fmaxf(red[tid], red[tid + s]);
        __syncthreads();
    }
    const float mx = red[0];
    __syncthreads();

    float ls = 0.f;
    for (int i = tid; i < HWs; i += 256) ls += expf(buf[i] - mx);
    red[tid] = ls;
    __syncthreads();
    #pragma unroll
    for (int s = 128; s > 0; s >>= 1) {
        if (tid < s) red[tid] += red[tid + s];
        __syncthreads();
    }
    if (tid == 0) {
        g_mx[b * HWs + m] = mx;
        g_si[b * HWs + m] = 1.f / red[0];
    }
}

// normalize + transpose: Pt[n, m] = exp(S[m,n]-mx[m]) * si[m]
__global__ void k_softmax_tr(const float* __restrict__ S, float* __restrict__ Pt) {
    __shared__ float tile[32][33];
    const int b = blockIdx.z;
    const size_t base = (size_t)b * HWs * HWs;
    const int m0 = blockIdx.y * 32, n0 = blockIdx.x * 32;
    const int lx = threadIdx.x & 31, ly = threadIdx.x >> 5;

    #pragma unroll
    for (int r = 0; r < 32; r += 8) {
        int m = m0 + ly + r;
        float v = S[base + (size_t)m * HWs + n0 + lx];
        tile[ly + r][lx] = expf(v - g_mx[b * HWs + m]) * g_si[b * HWs + m];
    }
    __syncthreads();
    #pragma unroll
    for (int r = 0; r < 32; r += 8) {
        int n = n0 + ly + r;
        Pt[base + (size_t)n * HWs + m0 + lx] = tile[lx][ly + r];
    }
}

// ------------------------------- launcher -----------------------------------
extern "C" void kernel_launch(void* const* d_in, const int* in_sizes, int n_in,
                              void* d_out, int out_size) {
    const float* x   = (const float*)d_in[0];
    const float* lnw = (const float*)d_in[1];
    const float* lnb = (const float*)d_in[2];
    const float* wq  = (const float*)d_in[3];
    const float* wk  = (const float*)d_in[4];
    const float* wv  = (const float*)d_in[5];
    const float* wp  = (const float*)d_in[6];
    const float* bp  = (const float*)d_in[7];
    float* out = (float*)d_out;

    float *p_hp, *p_q, *p_k, *p_v, *p_ao, *p_S, *p_Pt, *p_wkt, *p_wvt;
    cudaGetSymbolAddress((void**)&p_hp,  g_hp);
    cudaGetSymbolAddress((void**)&p_q,   g_q);
    cudaGetSymbolAddress((void**)&p_k,   g_k);
    cudaGetSymbolAddress((void**)&p_v,   g_v);
    cudaGetSymbolAddress((void**)&p_ao,  g_ao);
    cudaGetSymbolAddress((void**)&p_S,   g_S);
    cudaGetSymbolAddress((void**)&p_Pt,  g_Pt);
    cudaGetSymbolAddress((void**)&p_wkt, g_wkt);
    cudaGetSymbolAddress((void**)&p_wvt, g_wvt);

    // LN -> padded buffer (zero border), weight reorg
    k_zero<<<2048, 256>>>(p_hp, (size_t)NB * CH * PHWs);
    k_ln_stats<<<dim3(HWs / 256, NB), 256>>>(x);
    k_ln_apply<<<dim3(HWs / 256, CH, NB), 256>>>(x, lnw, lnb);
    k_reorg<<<CH * CH / 256, 256>>>(wk, p_wkt);
    k_reorg<<<CH * CH / 256, 256>>>(wv, p_wvt);

    // q / k / v
    k_conv<<<dim3(32, 4, NB), 256>>>(wq,    p_hp, p_q, 1);
    k_conv<<<dim3(32, 4, NB), 256>>>(p_wkt, p_hp, p_k, 9);
    k_conv<<<dim3(32, 4, NB), 256>>>(p_wvt, p_hp, p_v, 9);

    // S = scale * q^T k   [HW, HW] per batch
    const float scale = 0.044194173824159216f; // 512^-0.5
    k_gemm<true><<<dim3(32, 32, NB), 256>>>(
        p_q, p_k, p_S, CH, HWs, HWs, HWs, scale, nullptr, nullptr,
        (size_t)CH * HWs, (size_t)CH * HWs, (size_t)HWs * HWs);

    // softmax over n, write transposed probs
    k_softmax_stats<<<dim3(HWs, NB), 256>>>(p_S);
    k_softmax_tr<<<dim3(HWs / 32, HWs / 32, NB), 256>>>(p_S, p_Pt);

    // O = v @ Pt   [C, HW] per batch
    k_gemm<false><<<dim3(32, 4, NB), 256>>>(
        p_v, p_Pt, p_ao, HWs, HWs, HWs, HWs, 1.f, nullptr, nullptr,
        (size_t)CH * HWs, (size_t)HWs * HWs, (size_t)CH * HWs);

    // out = x + wp @ O + bp
    k_gemm<false><<<dim3(32, 4, NB), 256>>>(
        wp, p_ao, out, CH, CH, HWs, HWs, 1.f, bp, x,
        (size_t)0, (size_t)CH * HWs, (size_t)CH * HWs);
}

// round 3
// speedup vs baseline: 2.7425x; 2.7425x over previous
#include <cuda_runtime.h>
#include <cstdint>

// ===========================================================================
// AttnBlock via warp-level mma.sync tf32 (sm_100-safe, no 'a' features):
// LN -> q(1x1)/k(3x3)/v(3x3) convs -> spatial attention -> proj+bias+resid.
// B=4, C=512, H=W=64.  All matmuls are K-major GEMMs on tensor cores.
// ===========================================================================

namespace {
constexpr int CH   = 512;
constexpr int NB   = 4;
constexpr int HWs  = 4096;
constexpr int PWs  = 66;
constexpr int PHWs = PWs * PWs;   // 4356

constexpr int BM = 128, BN = 128, BK = 32, ST = 3;
constexpr int RS = 36;                         // padded row stride (floats)
constexpr int A_FLOATS = BM * RS;              // 4608
constexpr int STAGE_FLOATS = 2 * A_FLOATS;     // 9216
constexpr int SMEM_DYN = ST * STAGE_FLOATS * 4;// 110592 B
}

// ------------------------- scratch (device globals) ------------------------
__device__ float g_mu [NB * HWs];
__device__ float g_rs [NB * HWs];
__device__ float g_hpT[(size_t)NB * PHWs * CH];   // padded LN out, channel-last
__device__ float g_qT [(size_t)NB * HWs * CH];    // [p][c]
__device__ float g_kT [(size_t)NB * HWs * CH];    // [p][c]
__device__ float g_v  [(size_t)NB * CH * HWs];    // [c][p]
__device__ float g_aoT[(size_t)NB * HWs * CH];    // [p][c]
__device__ float g_S  [(size_t)NB * HWs * HWs];   // logits / probs (in place)
__device__ float g_wkt[(size_t)9 * CH * CH];      // [t][o][i]
__device__ float g_wvt[(size_t)9 * CH * CH];

// ------------------------------ PTX helpers --------------------------------
#define CP16(sa, g) \
    asm volatile("cp.async.cg.shared.global [%0], [%1], 16;" :: "r"(sa), "l"(g))
#define CP_COMMIT() asm volatile("cp.async.commit_group;" ::: "memory")
#define CP_WAIT(n)  asm volatile("cp.async.wait_group %0;" :: "n"(n) : "memory")

__device__ __forceinline__ uint32_t smem_u32(const void* p) {
    uint32_t a;
    asm("{ .reg .u64 t; cvta.to.shared.u64 t, %1; cvt.u32.u64 %0, t; }"
        : "=r"(a) : "l"(p));
    return a;
}

#define MMA_TF32(c, a, b) \
    asm volatile("mma.sync.aligned.m16n8k8.row.col.f32.tf32.tf32.f32 " \
        "{%0,%1,%2,%3}, {%4,%5,%6,%7}, {%8,%9}, {%0,%1,%2,%3};" \
        : "+f"((c)[0]), "+f"((c)[1]), "+f"((c)[2]), "+f"((c)[3]) \
        : "r"((a)[0]), "r"((a)[1]), "r"((a)[2]), "r"((a)[3]), \
          "r"((b)[0]), "r"((b)[1]))

// ------------------------------- small kernels ------------------------------
__global__ void k_zero(float* __restrict__ p, size_t n) {
    size_t i = (size_t)blockIdx.x * blockDim.x + threadIdx.x;
    size_t s = (size_t)gridDim.x * blockDim.x;
    for (; i < n; i += s) p[i] = 0.f;
}

__global__ void k_reorg(const float* __restrict__ w, float* __restrict__ wt) {
    int g = blockIdx.x * blockDim.x + threadIdx.x;
    #pragma unroll
    for (int t = 0; t < 9; t++)
        wt[(size_t)t * CH * CH + g] = w[(size_t)g * 9 + t];
}

__global__ void k_ln_stats(const float* __restrict__ x) {
    int p = blockIdx.x * blockDim.x + threadIdx.x;
    int b = blockIdx.y;
    const float* xb = x + (size_t)b * CH * HWs + p;
    float s = 0.f, s2 = 0.f;
    #pragma unroll 8
    for (int c = 0; c < CH; c++) {
        float v = xb[(size_t)c * HWs];
        s += v; s2 += v * v;
    }
    float mu = s * (1.f / CH);
    float var = s2 * (1.f / CH) - mu * mu;
    g_mu[b * HWs + p] = mu;
    g_rs[b * HWs + p] = rsqrtf(var + 1e-6f);
}

// LN + transpose to channel-last padded hpT[spo(p)][c]
__global__ void k_ln_applyT(const float* __restrict__ x,
                            const float* __restrict__ lw,
                            const float* __restrict__ lb,
                            float* __restrict__ hpT) {
    __shared__ float t[32][33];
    const int b = blockIdx.z;
    const int c0 = blockIdx.y * 32, p0 = blockIdx.x * 32;
    const int lx = threadIdx.x & 31, ly = threadIdx.x >> 5;
    const int p = p0 + lx;
    const float mu = g_mu[b * HWs + p];
    const float rs = g_rs[b * HWs + p];
    #pragma unroll
    for (int r = 0; r < 32; r += 8) {
        int c = c0 + ly + r;
        float v = x[((size_t)b * CH + c) * HWs + p];
        t[ly + r][lx] = (v - mu) * rs * lw[c] + lb[c];
    }
    __syncthreads();
    #pragma unroll
    for (int r = 0; r < 32; r += 8) {
        int pp = p0 + ly + r;
        int spo = ((pp >> 6) + 1) * PWs + (pp & 63) + 1;
        hpT[((size_t)b * PHWs + spo) * CH + c0 + lx] = t[lx][ly + r];
    }
}

__global__ void k_softmax_inplace(float* __restrict__ S) {
    const int m = blockIdx.x, b = blockIdx.y;
    float* row = S + ((size_t)b * HWs + m) * HWs;
    __shared__ float buf[HWs];
    __shared__ float red[256];
    const int tid = threadIdx.x;

    float lmax = -1e30f;
    for (int i = tid; i < HWs; i += 256) {
        float v = row[i];
        buf[i] = v;
        lmax = fmaxf(lmax, v);
    }
    red[tid] = lmax;
    __syncthreads();
    #pragma unroll
    for (int s = 128; s > 0; s >>= 1) {
        if (tid < s) red[tid] = fmaxf(red[tid], red[tid + s]);
        __syncthreads();
    }
    const float mx = red[0];
    __syncthreads();
    float ls = 0.f;
    for (int i = tid; i < HWs; i += 256) ls += expf(buf[i] - mx);
    red[tid] = ls;
    __syncthreads();
    #pragma unroll
    for (int s = 128; s > 0; s >>= 1) {
        if (tid < s) red[tid] += red[tid + s];
        __syncthreads();
    }
    const float inv = 1.f / red[0];
    __syncthreads();
    for (int i = tid; i < HWs; i += 256)
        row[i] = expf(buf[i] - mx) * inv;
}

// ---------------------- unified tf32 mma.sync GEMM --------------------------
// D[128,128] tile: acc[m,n] = sum_k A[m,k]*B[n,k]  (both K-major).
// taps==0: dense A(lda)/B(ldb).  taps==1: B gathered from hpT via spo(p).
// taps==9: A per-tap slabs (+t*CH*CH), B rows shifted by tap offset.
// epiCol==0: C[m*ldc+n] = alpha*acc (+bias[m]) (+resid[m*ldc+n])
// epiCol==1: C[n*ldc+m] = alpha*acc
__global__ void __launch_bounds__(256, 1)
tgemm(const float* __restrict__ A, const float* __restrict__ B,
      float* __restrict__ C, const float* __restrict__ resid,
      const float* __restrict__ bias,
      int KT, int taps, int lda, int ldb, int ldc,
      size_t sA, size_t sB, size_t sC, float alpha, int epiCol) {
    extern __shared__ float dsm[];
    const int tid = threadIdx.x;
    const int lane = tid & 31;
    const int w  = tid >> 5;
    const int wm = (w & 3) * 32;     // warp m offset
    const int wn = (w >> 2) * 64;    // warp n offset
    const int g  = lane >> 2;        // group id
    const int t  = lane & 3;         // thread-in-group

    const int mBase = blockIdx.y * BM, nBase = blockIdx.x * BN;
    A += blockIdx.z * sA;
    B += blockIdx.z * sB;
    C += blockIdx.z * sC;
    if (resid) resid += blockIdx.z * sC;

    // ---- producer thread-invariant addressing (4 A chunks, 4 B chunks) ----
    uint32_t aSm[4], bSm[4];     // smem byte offsets within a stage
    size_t   aG[4];              // gmem row offsets (dense part)
    int      bSpo[4];            // padded-spatial row for conv gather
    size_t   bG[4];              // gmem row offsets (dense B)
    const uint32_t smBase = smem_u32(dsm);
    #pragma unroll
    for (int i = 0; i < 4; i++) {
        int chunk = tid + 256 * i;
        int r = chunk >> 3, q = chunk & 7;
        aSm[i] = (uint32_t)(r * RS + q * 4) * 4u;
        bSm[i] = (uint32_t)(A_FLOATS + r * RS + q * 4) * 4u;
        aG[i]  = (size_t)(mBase + r) * lda + q * 4;
        int p  = nBase + r;
        bSpo[i] = ((p >> 6) + 1) * PWs + (p & 63) + 1;
        bG[i]  = (size_t)p * ldb + q * 4;
    }

    float acc[2][8][4];
    #pragma unroll
    for (int mt = 0; mt < 2; mt++)
        #pragma unroll
        for (int nt = 0; nt < 8; nt++)
            #pragma unroll
            for (int e = 0; e < 4; e++) acc[mt][nt][e] = 0.f;

    // ---- issue one k-tile of cp.async (or empty commit) ----
    auto issue = [&](int kt) {
        if (kt < KT) {
            const int s = kt % ST;
            const uint32_t sb = smBase + (uint32_t)(s * STAGE_FLOATS) * 4u;
            const int kg = kt * BK;
            const float* Ab;
            int kc, off;
            if (taps) {
                const int tp = kg >> 9;
                kc = kg & 511;
                Ab = A + ((size_t)tp << 18);
                off = (taps == 9) ? ((tp / 3 - 1) * PWs + (tp % 3 - 1)) : 0;
            } else { Ab = A; kc = kg; off = 0; }
            #pragma unroll
            for (int i = 0; i < 4; i++)
                CP16(sb + aSm[i], Ab + aG[i] + kc);
            if (taps) {
                #pragma unroll
                for (int i = 0; i < 4; i++)
                    CP16(sb + bSm[i],
                         B + (((size_t)(bSpo[i] + off)) << 9) + kc + ((tid + 256 * i) & 7) * 4);
            } else {
                #pragma unroll
                for (int i = 0; i < 4; i++)
                    CP16(sb + bSm[i], B + bG[i] + kg);
            }
        }
        CP_COMMIT();
    };

    issue(0);
    issue(1);

    for (int kt = 0; kt < KT; kt++) {
        CP_WAIT(1);
        __syncthreads();
        issue(kt + 2);

        const float* As = dsm + (kt % ST) * STAGE_FLOATS;
        const float* Bs = As + A_FLOATS;
        #pragma unroll
        for (int ks = 0; ks < 4; ks++) {
            const int ko = ks * 8;
            uint32_t a[2][4], b[8][2];
            #pragma unroll
            for (int mt = 0; mt < 2; mt++) {
                const int r0 = wm + mt * 16 + g;
                a[mt][0] = __float_as_uint(As[r0 * RS + ko + t]);
                a[mt][1] = __float_as_uint(As[(r0 + 8) * RS + ko + t]);
                a[mt][2] = __float_as_uint(As[r0 * RS + ko + t + 4]);
                a[mt][3] = __float_as_uint(As[(r0 + 8) * RS + ko + t + 4]);
            }
            #pragma unroll
            for (int nt = 0; nt < 8; nt++) {
                const int n0 = wn + nt * 8 + g;
                b[nt][0] = __float_as_uint(Bs[n0 * RS + ko + t]);
                b[nt][1] = __float_as_uint(Bs[n0 * RS + ko + t + 4]);
            }
            #pragma unroll
            for (int mt = 0; mt < 2; mt++)
                #pragma unroll
                for (int nt = 0; nt < 8; nt++)
                    MMA_TF32(acc[mt][nt], a[mt], b[nt]);
        }
    }

    // ------------------------------ epilogue --------------------------------
    if (!epiCol) {
        #pragma unroll
        for (int mt = 0; mt < 2; mt++) {
            const int r0 = mBase + wm + mt * 16 + g;
            const int r1 = r0 + 8;
            const float bv0 = bias ? bias[r0] : 0.f;
            const float bv1 = bias ? bias[r1] : 0.f;
            #pragma unroll
            for (int nt = 0; nt < 8; nt++) {
                const int cc = nBase + wn + nt * 8 + 2 * t;
                float2 o0, o1;
                o0.x = acc[mt][nt][0] * alpha + bv0;
                o0.y = acc[mt][nt][1] * alpha + bv0;
                o1.x = acc[mt][nt][2] * alpha + bv1;
                o1.y = acc[mt][nt][3] * alpha + bv1;
                if (resid) {
                    float2 q0 = *(const float2*)&resid[(size_t)r0 * ldc + cc];
                    float2 q1 = *(const float2*)&resid[(size_t)r1 * ldc + cc];
                    o0.x += q0.x; o0.y += q0.y;
                    o1.x += q1.x; o1.y += q1.y;
                }
                *(float2*)&C[(size_t)r0 * ldc + cc] = o0;
                *(float2*)&C[(size_t)r1 * ldc + cc] = o1;
            }
        }
    } else {
        #pragma unroll
        for (int mt = 0; mt < 2; mt++) {
            const int r0 = mBase + wm + mt * 16 + g;
            const int r1 = r0 + 8;
            #pragma unroll
            for (int nt = 0; nt < 8; nt++) {
                const int cc = nBase + wn + nt * 8 + 2 * t;
                C[(size_t)cc * ldc + r0]       = acc[mt][nt][0] * alpha;
                C[(size_t)(cc + 1) * ldc + r0] = acc[mt][nt][1] * alpha;
                C[(size_t)cc * ldc + r1]       = acc[mt][nt][2] * alpha;
                C[(size_t)(cc + 1) * ldc + r1] = acc[mt][nt][3] * alpha;
            }
        }
    }
}

// ------------------------------- launcher -----------------------------------
extern "C" void kernel_launch(void* const* d_in, const int* in_sizes, int n_in,
                              void* d_out, int out_size) {
    const float* x   = (const float*)d_in[0];
    const float* lnw = (const float*)d_in[1];
    const float* lnb = (const float*)d_in[2];
    const float* wq  = (const float*)d_in[3];
    const float* wk  = (const float*)d_in[4];
    const float* wv  = (const float*)d_in[5];
    const float* wp  = (const float*)d_in[6];
    const float* bp  = (const float*)d_in[7];
    float* out = (float*)d_out;

    float *p_hpT, *p_qT, *p_kT, *p_v, *p_aoT, *p_S, *p_wkt, *p_wvt;
    cudaGetSymbolAddress((void**)&p_hpT, g_hpT);
    cudaGetSymbolAddress((void**)&p_qT,  g_qT);
    cudaGetSymbolAddress((void**)&p_kT,  g_kT);
    cudaGetSymbolAddress((void**)&p_v,   g_v);
    cudaGetSymbolAddress((void**)&p_aoT, g_aoT);
    cudaGetSymbolAddress((void**)&p_S,   g_S);
    cudaGetSymbolAddress((void**)&p_wkt, g_wkt);
    cudaGetSymbolAddress((void**)&p_wvt, g_wvt);

    cudaFuncSetAttribute(tgemm, cudaFuncAttributeMaxDynamicSharedMemorySize,
                         SMEM_DYN);

    // LN -> channel-last padded hpT; weight reorg
    k_zero<<<2048, 256>>>(p_hpT, (size_t)NB * PHWs * CH);
    k_ln_stats<<<dim3(HWs / 256, NB), 256>>>(x);
    k_ln_applyT<<<dim3(HWs / 32, CH / 32, NB), 256>>>(x, lnw, lnb, p_hpT);
    k_reorg<<<CH * CH / 256, 256>>>(wk, p_wkt);
    k_reorg<<<CH * CH / 256, 256>>>(wv, p_wvt);

    const size_t sHP = (size_t)PHWs * CH;
    const size_t sPC = (size_t)HWs * CH;
    const size_t sSS = (size_t)HWs * HWs;

    // q = wq * hpT (1x1) -> qT[p][c]
    tgemm<<<dim3(32, 4, NB), 256, SMEM_DYN>>>(
        wq, p_hpT, p_qT, nullptr, nullptr,
        16, 1, CH, 0, CH, 0, sHP, sPC, 1.f, 1);
    // k = wk (*) hpT (3x3) -> kT[p][c]
    tgemm<<<dim3(32, 4, NB), 256, SMEM_DYN>>>(
        p_wkt, p_hpT, p_kT, nullptr, nullptr,
        144, 9, CH, 0, CH, 0, sHP, sPC, 1.f, 1);
    // v = wv (*) hpT (3x3) -> v[c][p]
    tgemm<<<dim3(32, 4, NB), 256, SMEM_DYN>>>(
        p_wvt, p_hpT, p_v, nullptr, nullptr,
        144, 9, CH, 0, HWs, 0, sHP, sPC, 1.f, 0);

    // S[m,n] = scale * sum_c qT[m,c] kT[n,c]
    const float scale = 0.044194173824159216f;  // 512^-0.5
    tgemm<<<dim3(32, 32, NB), 256, SMEM_DYN>>>(
        p_qT, p_kT, p_S, nullptr, nullptr,
        16, 0, CH, CH, HWs, sPC, sPC, sSS, scale, 0);

    // softmax rows of S, in place -> P
    k_softmax_inplace<<<dim3(HWs, NB), 256>>>(p_S);

    // O[c,m] = sum_n v[c,n] P[m,n] -> aoT[m][c]
    tgemm<<<dim3(32, 4, NB), 256, SMEM_DYN>>>(
        p_v, p_S, p_aoT, nullptr, nullptr,
        128, 0, HWs, HWs, CH, sPC, sSS, sPC, 1.f, 1);

    // out[o,p] = x + wp*aoT + bp
    tgemm<<<dim3(32, 4, NB), 256, SMEM_DYN>>>(
        wp, p_aoT, out, x, bp,
        16, 0, CH, CH, HWs, 0, sPC, sPC, 1.f, 0);
}

// round 4
// speedup vs baseline: 4.1356x; 1.5080x over previous
#include <cuda_runtime.h>
#include <cuda_fp16.h>
#include <cstdint>

// ===========================================================================
// AttnBlock via mma.sync m16n8k16 fp16 (fp32 accum), sm_100-safe.
// LN -> q(1x1)/k(3x3)/v(3x3) convs -> spatial attention -> proj+bias+resid.
// B=4, C=512, H=W=64.  fp16 operands everywhere (same mantissa as tf32),
// fp32 accumulation, fp32 logits + softmax, fp16 probs.
// ===========================================================================

namespace {
constexpr int CH   = 512;
constexpr int NB   = 4;
constexpr int HWs  = 4096;
constexpr int PWs  = 66;
constexpr int PHWs = PWs * PWs;   // 4356

constexpr int BM = 128, BN = 128, BK = 32, ST = 3;
constexpr int RS = 40;                           // padded row stride (halfs)
constexpr int A_HALFS = BM * RS;                 // 5120
constexpr int A_BYTES = A_HALFS * 2;             // 10240
constexpr int STAGE_BYTES = 2 * A_BYTES;         // 20480
constexpr int SMEM_DYN = ST * STAGE_BYTES;       // 61440
}

// ------------------------- scratch (device globals) ------------------------
__device__ float  g_mu [NB * HWs];
__device__ float  g_rs [NB * HWs];
__device__ __half g_hpT[(size_t)NB * PHWs * CH];   // padded LN out, channel-last
__device__ __half g_qT [(size_t)NB * HWs * CH];    // [p][c]
__device__ __half g_kT [(size_t)NB * HWs * CH];    // [p][c]
__device__ __half g_v  [(size_t)NB * CH * HWs];    // [c][p]
__device__ __half g_aoT[(size_t)NB * HWs * CH];    // [p][c]
__device__ float  g_S  [(size_t)NB * HWs * HWs];   // fp32 logits
__device__ __half g_P  [(size_t)NB * HWs * HWs];   // fp16 probs
__device__ __half g_wkt[(size_t)9 * CH * CH];      // [t][o][i] fp16
__device__ __half g_wvt[(size_t)9 * CH * CH];
__device__ __half g_wqh[(size_t)CH * CH];
__device__ __half g_wph[(size_t)CH * CH];

// ------------------------------ PTX helpers --------------------------------
#define CP16(sa, g) \
    asm volatile("cp.async.cg.shared.global [%0], [%1], 16;" :: "r"(sa), "l"(g))
#define CP_COMMIT() asm volatile("cp.async.commit_group;" ::: "memory")
#define CP_WAIT(n)  asm volatile("cp.async.wait_group %0;" :: "n"(n) : "memory")

__device__ __forceinline__ uint32_t smem_u32(const void* p) {
    uint32_t a;
    asm("{ .reg .u64 t; cvta.to.shared.u64 t, %1; cvt.u32.u64 %0, t; }"
        : "=r"(a) : "l"(p));
    return a;
}

#define MMA_F16(c, a, b) \
    asm volatile("mma.sync.aligned.m16n8k16.row.col.f32.f16.f16.f32 " \
        "{%0,%1,%2,%3}, {%4,%5,%6,%7}, {%8,%9}, {%0,%1,%2,%3};" \
        : "+f"((c)[0]), "+f"((c)[1]), "+f"((c)[2]), "+f"((c)[3]) \
        : "r"((a)[0]), "r"((a)[1]), "r"((a)[2]), "r"((a)[3]), \
          "r"((b)[0]), "r"((b)[1]))

// ------------------------------- small kernels ------------------------------
__global__ void k_zero32(uint32_t* __restrict__ p, size_t n) {
    size_t i = (size_t)blockIdx.x * blockDim.x + threadIdx.x;
    size_t s = (size_t)gridDim.x * blockDim.x;
    for (; i < n; i += s) p[i] = 0u;
}

__global__ void k_cvt(const float* __restrict__ w, __half* __restrict__ h, int n) {
    int i = blockIdx.x * blockDim.x + threadIdx.x;
    if (i < n) h[i] = __float2half(w[i]);
}

// reorg conv weight [O,I,3,3] (fp32) -> [t][O][I] (fp16)
__global__ void k_reorg(const float* __restrict__ w, __half* __restrict__ wt) {
    int g = blockIdx.x * blockDim.x + threadIdx.x;
    #pragma unroll
    for (int t = 0; t < 9; t++)
        wt[(size_t)t * CH * CH + g] = __float2half(w[(size_t)g * 9 + t]);
}

__global__ void k_ln_stats(const float* __restrict__ x) {
    int p = blockIdx.x * blockDim.x + threadIdx.x;
    int b = blockIdx.y;
    const float* xb = x + (size_t)b * CH * HWs + p;
    float s = 0.f, s2 = 0.f;
    #pragma unroll 8
    for (int c = 0; c < CH; c++) {
        float v = xb[(size_t)c * HWs];
        s += v; s2 += v * v;
    }
    float mu = s * (1.f / CH);
    float var = s2 * (1.f / CH) - mu * mu;
    g_mu[b * HWs + p] = mu;
    g_rs[b * HWs + p] = rsqrtf(var + 1e-6f);
}

// LN + transpose to channel-last padded hpT[spo(p)][c] (fp16)
__global__ void k_ln_applyT(const float* __restrict__ x,
                            const float* __restrict__ lw,
                            const float* __restrict__ lb,
                            __half* __restrict__ hpT) {
    __shared__ float t[32][33];
    const int b = blockIdx.z;
    const int c0 = blockIdx.y * 32, p0 = blockIdx.x * 32;
    const int lx = threadIdx.x & 31, ly = threadIdx.x >> 5;
    const int p = p0 + lx;
    const float mu = g_mu[b * HWs + p];
    const float rs = g_rs[b * HWs + p];
    #pragma unroll
    for (int r = 0; r < 32; r += 8) {
        int c = c0 + ly + r;
        float v = x[((size_t)b * CH + c) * HWs + p];
        t[ly + r][lx] = (v - mu) * rs * lw[c] + lb[c];
    }
    __syncthreads();
    #pragma unroll
    for (int r = 0; r < 32; r += 8) {
        int pp = p0 + ly + r;
        int spo = ((pp >> 6) + 1) * PWs + (pp & 63) + 1;
        hpT[((size_t)b * PHWs + spo) * CH + c0 + lx] = __float2half(t[lx][ly + r]);
    }
}

// softmax: fp32 logits row -> fp16 probs row
__global__ void k_softmax(const float* __restrict__ S, __half* __restrict__ P) {
    const int m = blockIdx.x, b = blockIdx.y;
    const float* row = S + ((size_t)b * HWs + m) * HWs;
    __half* prow = P + ((size_t)b * HWs + m) * HWs;
    __shared__ float buf[HWs];
    __shared__ float red[256];
    const int tid = threadIdx.x;

    float lmax = -1e30f;
    for (int i = tid; i < HWs; i += 256) {
        float v = row[i];
        buf[i] = v;
        lmax = fmaxf(lmax, v);
    }
    red[tid] = lmax;
    __syncthreads();
    #pragma unroll
    for (int s = 128; s > 0; s >>= 1) {
        if (tid < s) red[tid] = fmaxf(red[tid], red[tid + s]);
        __syncthreads();
    }
    const float mx = red[0];
    __syncthreads();
    float ls = 0.f;
    for (int i = tid; i < HWs; i += 256) ls += __expf(buf[i] - mx);
    red[tid] = ls;
    __syncthreads();
    #pragma unroll
    for (int s = 128; s > 0; s >>= 1) {
        if (tid < s) red[tid] += red[tid + s];
        __syncthreads();
    }
    const float inv = 1.f / red[0];
    __syncthreads();
    for (int i = tid; i < HWs; i += 256)
        prow[i] = __float2half(__expf(buf[i] - mx) * inv);
}

// ---------------------- unified fp16 mma.sync GEMM --------------------------
// acc[m,n] = sum_k A[m,k]*B[n,k]  (both K-major fp16).
// taps==0: dense A(lda)/B(ldb).  taps==1: B gathered from hpT via spo(p).
// taps==9: A per-tap slabs (+t*CH*CH), B rows shifted by tap offset.
// epiMode 0: float C[m*ldc+n] = alpha*acc (+bias[m]) (+resid[m*ldc+n])
// epiMode 1: half  C[n*ldc+m] = alpha*acc   (transposed)
// epiMode 2: half  C[m*ldc+n] = alpha*acc
__global__ void __launch_bounds__(256, 1)
tgemm(const __half* __restrict__ A, const __half* __restrict__ B,
      void* __restrict__ Cv, const float* __restrict__ resid,
      const float* __restrict__ bias,
      int KT, int taps, int lda, int ldb, int ldc,
      size_t sA, size_t sB, size_t sC, float alpha, int epiMode) {
    extern __shared__ char dsm[];
    __half* smh = (__half*)dsm;
    const int tid = threadIdx.x;
    const int lane = tid & 31;
    const int w  = tid >> 5;
    const int wm = (w & 3) * 32;     // warp m offset
    const int wn = (w >> 2) * 64;    // warp n offset
    const int g  = lane >> 2;
    const int t  = lane & 3;

    const int mBase = blockIdx.y * BM, nBase = blockIdx.x * BN;
    A += blockIdx.z * sA;
    B += blockIdx.z * sB;
    if (resid) resid += blockIdx.z * sC;

    // ---- producer addressing: 2 A chunks + 2 B chunks of 16B per thread ----
    uint32_t aSm[2], bSm[2];
    size_t   aG[2], bG[2];
    int      bSpo[2], bQ[2];
    const uint32_t smBase = smem_u32(dsm);
    #pragma unroll
    for (int i = 0; i < 2; i++) {
        int chunk = tid + 256 * i;
        int r = chunk >> 2, q = chunk & 3;
        aSm[i] = (uint32_t)(r * RS + q * 8) * 2u;
        bSm[i] = (uint32_t)A_BYTES + aSm[i];
        aG[i]  = (size_t)(mBase + r) * lda + q * 8;
        int p  = nBase + r;
        bSpo[i] = ((p >> 6) + 1) * PWs + (p & 63) + 1;
        bQ[i]   = q * 8;
        bG[i]  = (size_t)p * ldb + q * 8;
    }

    float acc[2][8][4];
    #pragma unroll
    for (int mt = 0; mt < 2; mt++)
        #pragma unroll
        for (int nt = 0; nt < 8; nt++)
            #pragma unroll
            for (int e = 0; e < 4; e++) acc[mt][nt][e] = 0.f;

    auto issue = [&](int kt) {
        if (kt < KT) {
            const int s = kt % ST;
            const uint32_t sb = smBase + (uint32_t)(s * STAGE_BYTES);
            const int kg = kt * BK;
            const __half* Ab;
            int kc, off;
            if (taps) {
                const int tp = kg >> 9;
                kc = kg & 511;
                Ab = A + ((size_t)tp << 18);
                off = (taps == 9) ? ((tp / 3 - 1) * PWs + (tp % 3 - 1)) : 0;
            } else { Ab = A; kc = kg; off = 0; }
            #pragma unroll
            for (int i = 0; i < 2; i++)
                CP16(sb + aSm[i], Ab + aG[i] + kc);
            if (taps) {
                #pragma unroll
                for (int i = 0; i < 2; i++)
                    CP16(sb + bSm[i],
                         B + (((size_t)(bSpo[i] + off)) << 9) + kc + bQ[i]);
            } else {
                #pragma unroll
                for (int i = 0; i < 2; i++)
                    CP16(sb + bSm[i], B + bG[i] + kg);
            }
        }
        CP_COMMIT();
    };

    issue(0);
    issue(1);

    for (int kt = 0; kt < KT; kt++) {
        CP_WAIT(1);
        __syncthreads();
        issue(kt + 2);

        const __half* As = smh + (kt % ST) * (STAGE_BYTES / 2);
        const __half* Bs = As + A_HALFS;
        #pragma unroll
        for (int ks = 0; ks < 2; ks++) {
            const int ko = ks * 16;
            uint32_t a[2][4], b[8][2];
            #pragma unroll
            for (int mt = 0; mt < 2; mt++) {
                const int r0 = wm + mt * 16 + g;
                a[mt][0] = *(const uint32_t*)&As[r0 * RS + ko + 2 * t];
                a[mt][1] = *(const uint32_t*)&As[(r0 + 8) * RS + ko + 2 * t];
                a[mt][2] = *(const uint32_t*)&As[r0 * RS + ko + 8 + 2 * t];
                a[mt][3] = *(const uint32_t*)&As[(r0 + 8) * RS + ko + 8 + 2 * t];
            }
            #pragma unroll
            for (int nt = 0; nt < 8; nt++) {
                const int n0 = wn + nt * 8 + g;
                b[nt][0] = *(const uint32_t*)&Bs[n0 * RS + ko + 2 * t];
                b[nt][1] = *(const uint32_t*)&Bs[n0 * RS + ko + 8 + 2 * t];
            }
            #pragma unroll
            for (int mt = 0; mt < 2; mt++)
                #pragma unroll
                for (int nt = 0; nt < 8; nt++)
                    MMA_F16(acc[mt][nt], a[mt], b[nt]);
        }
    }

    // ------------------------------ epilogue --------------------------------
    if (epiMode == 0) {
        float* C = (float*)Cv + blockIdx.z * sC;
        #pragma unroll
        for (int mt = 0; mt < 2; mt++) {
            const int r0 = mBase + wm + mt * 16 + g;
            const int r1 = r0 + 8;
            const float bv0 = bias ? bias[r0] : 0.f;
            const float bv1 = bias ? bias[r1] : 0.f;
            #pragma unroll
            for (int nt = 0; nt < 8; nt++) {
                const int cc = nBase + wn + nt * 8 + 2 * t;
                float2 o0, o1;
                o0.x = acc[mt][nt][0] * alpha + bv0;
                o0.y = acc[mt][nt][1] * alpha + bv0;
                o1.x = acc[mt][nt][2] * alpha + bv1;
                o1.y = acc[mt][nt][3] * alpha + bv1;
                if (resid) {
                    float2 q0 = *(const float2*)&resid[(size_t)r0 * ldc + cc];
                    float2 q1 = *(const float2*)&resid[(size_t)r1 * ldc + cc];
                    o0.x += q0.x; o0.y += q0.y;
                    o1.x += q1.x; o1.y += q1.y;
                }
                *(float2*)&C[(size_t)r0 * ldc + cc] = o0;
                *(float2*)&C[(size_t)r1 * ldc + cc] = o1;
            }
        }
    } else if (epiMode == 1) {
        __half* C = (__half*)Cv + blockIdx.z * sC;
        #pragma unroll
        for (int mt = 0; mt < 2; mt++) {
            const int r0 = mBase + wm + mt * 16 + g;
            const int r1 = r0 + 8;
            #pragma unroll
            for (int nt = 0; nt < 8; nt++) {
                const int cc = nBase + wn + nt * 8 + 2 * t;
                C[(size_t)cc * ldc + r0]       = __float2half(acc[mt][nt][0] * alpha);
                C[(size_t)(cc + 1) * ldc + r0] = __float2half(acc[mt][nt][1] * alpha);
                C[(size_t)cc * ldc + r1]       = __float2half(acc[mt][nt][2] * alpha);
                C[(size_t)(cc + 1) * ldc + r1] = __float2half(acc[mt][nt][3] * alpha);
            }
        }
    } else {
        __half* C = (__half*)Cv + blockIdx.z * sC;
        #pragma unroll
        for (int mt = 0; mt < 2; mt++) {
            const int r0 = mBase + wm + mt * 16 + g;
            const int r1 = r0 + 8;
            #pragma unroll
            for (int nt = 0; nt < 8; nt++) {
                const int cc = nBase + wn + nt * 8 + 2 * t;
                __half2 h0 = __floats2half2_rn(acc[mt][nt][0] * alpha,
                                               acc[mt][nt][1] * alpha);
                __half2 h1 = __floats2half2_rn(acc[mt][nt][2] * alpha,
                                               acc[mt][nt][3] * alpha);
                *(__half2*)&C[(size_t)r0 * ldc + cc] = h0;
                *(__half2*)&C[(size_t)r1 * ldc + cc] = h1;
            }
        }
    }
}

// ------------------------------- launcher -----------------------------------
extern "C" void kernel_launch(void* const* d_in, const int* in_sizes, int n_in,
                              void* d_out, int out_size) {
    const float* x   = (const float*)d_in[0];
    const float* lnw = (const float*)d_in[1];
    const float* lnb = (const float*)d_in[2];
    const float* wq  = (const float*)d_in[3];
    const float* wk  = (const float*)d_in[4];
    const float* wv  = (const float*)d_in[5];
    const float* wp  = (const float*)d_in[6];
    const float* bp  = (const float*)d_in[7];
    float* out = (float*)d_out;

    __half *p_hpT, *p_qT, *p_kT, *p_v, *p_aoT, *p_P, *p_wkt, *p_wvt, *p_wqh, *p_wph;
    float *p_S;
    cudaGetSymbolAddress((void**)&p_hpT, g_hpT);
    cudaGetSymbolAddress((void**)&p_qT,  g_qT);
    cudaGetSymbolAddress((void**)&p_kT,  g_kT);
    cudaGetSymbolAddress((void**)&p_v,   g_v);
    cudaGetSymbolAddress((void**)&p_aoT, g_aoT);
    cudaGetSymbolAddress((void**)&p_S,   g_S);
    cudaGetSymbolAddress((void**)&p_P,   g_P);
    cudaGetSymbolAddress((void**)&p_wkt, g_wkt);
    cudaGetSymbolAddress((void**)&p_wvt, g_wvt);
    cudaGetSymbolAddress((void**)&p_wqh, g_wqh);
    cudaGetSymbolAddress((void**)&p_wph, g_wph);

    cudaFuncSetAttribute(tgemm, cudaFuncAttributeMaxDynamicSharedMemorySize,
                         SMEM_DYN);

    // LN -> channel-last padded hpT (fp16); weight conversion/reorg
    k_zero32<<<2048, 256>>>((uint32_t*)p_hpT, (size_t)NB * PHWs * CH / 2);
    k_ln_stats<<<dim3(HWs / 256, NB), 256>>>(x);
    k_ln_applyT<<<dim3(HWs / 32, CH / 32, NB), 256>>>(x, lnw, lnb, p_hpT);
    k_reorg<<<CH * CH / 256, 256>>>(wk, p_wkt);
    k_reorg<<<CH * CH / 256, 256>>>(wv, p_wvt);
    k_cvt<<<CH * CH / 256, 256>>>(wq, p_wqh, CH * CH);
    k_cvt<<<CH * CH / 256, 256>>>(wp, p_wph, CH * CH);

    const size_t sHP = (size_t)PHWs * CH;
    const size_t sPC = (size_t)HWs * CH;
    const size_t sSS = (size_t)HWs * HWs;

    // q = wq * hpT (1x1) -> qT[p][c] fp16
    tgemm<<<dim3(32, 4, NB), 256, SMEM_DYN>>>(
        p_wqh, p_hpT, p_qT, nullptr, nullptr,
        16, 1, CH, 0, CH, 0, sHP, sPC, 1.f, 1);
    // k = wk (*) hpT (3x3) -> kT[p][c] fp16
    tgemm<<<dim3(32, 4, NB), 256, SMEM_DYN>>>(
        p_wkt, p_hpT, p_kT, nullptr, nullptr,
        144, 9, CH, 0, CH, 0, sHP, sPC, 1.f, 1);
    // v = wv (*) hpT (3x3) -> v[c][p] fp16
    tgemm<<<dim3(32, 4, NB), 256, SMEM_DYN>>>(
        p_wvt, p_hpT, p_v, nullptr, nullptr,
        144, 9, CH, 0, HWs, 0, sHP, sPC, 1.f, 2);

    // S[m,n] = scale * sum_c qT[m,c] kT[n,c]  (fp32 logits)
    const float scale = 0.044194173824159216f;  // 512^-0.5
    tgemm<<<dim3(32, 32, NB), 256, SMEM_DYN>>>(
        p_qT, p_kT, p_S, nullptr, nullptr,
        16, 0, CH, CH, HWs, sPC, sPC, sSS, scale, 0);

    // softmax rows: fp32 logits -> fp16 probs
    k_softmax<<<dim3(HWs, NB), 256>>>(p_S, p_P);

    // O[c,m] = sum_n v[c,n] P[m,n] -> aoT[m][c] fp16
    tgemm<<<dim3(32, 4, NB), 256, SMEM_DYN>>>(
        p_v, p_P, p_aoT, nullptr, nullptr,
        128, 0, HWs, HWs, CH, sPC, sSS, sPC, 1.f, 1);

    // out[o,p] = x + wp*aoT + bp  (fp32)
    tgemm<<<dim3(32, 4, NB), 256, SMEM_DYN>>>(
        p_wph, p_aoT, out, x, bp,
        16, 0, CH, CH, HWs, 0, sPC, sPC, 1.f, 0);
}

// round 5
// speedup vs baseline: 4.9447x; 1.1956x over previous
#include <cuda_runtime.h>
#include <cuda_fp16.h>
#include <cstdint>

// ===========================================================================
// AttnBlock via mma.sync m16n8k16 fp16 (fp32 accum), sm_100-safe.
// All GEMMs oriented so every output store is row-major coalesced:
//   q/k convs:  M=p (A = tap-gathered hpT), N=o (B = weights)   -> [p][c]
//   v conv:     M=o (A = weights),          N=p (B = gathered)  -> [c][p]
//   S:          A=qT, B=kT (both [p][c])                        -> fp32 [m][n]
//   O:          M=p (A = P row-major), N=c (B = v [c][n])       -> [p][c]
//   proj:       A=wp, B=aoT [p][c], bias+residual fused         -> fp32 out
// ===========================================================================

namespace {
constexpr int CH   = 512;
constexpr int NB   = 4;
constexpr int HWs  = 4096;
constexpr int PWs  = 66;
constexpr int PHWs = PWs * PWs;   // 4356

constexpr int BM = 128, BN = 128, BK = 32, ST = 3;
constexpr int RS = 40;                           // padded row stride (halfs)
constexpr int A_HALFS = BM * RS;                 // 5120
constexpr int A_BYTES = A_HALFS * 2;             // 10240
constexpr int STAGE_BYTES = 2 * A_BYTES;         // 20480
constexpr int SMEM_DYN = ST * STAGE_BYTES;       // 61440
}

// ------------------------- scratch (device globals) ------------------------
__device__ float  g_mu [NB * HWs];
__device__ float  g_rs [NB * HWs];
__device__ __half g_hpT[(size_t)NB * PHWs * CH];   // padded LN out, channel-last
__device__ __half g_qT [(size_t)NB * HWs * CH];    // [p][c]
__device__ __half g_kT [(size_t)NB * HWs * CH];    // [p][c]
__device__ __half g_v  [(size_t)NB * CH * HWs];    // [c][p]
__device__ __half g_aoT[(size_t)NB * HWs * CH];    // [p][c]
__device__ float  g_S  [(size_t)NB * HWs * HWs];   // fp32 logits
__device__ __half g_P  [(size_t)NB * HWs * HWs];   // fp16 probs
__device__ __half g_wkt[(size_t)9 * CH * CH];      // [t][o][i] fp16
__device__ __half g_wvt[(size_t)9 * CH * CH];
__device__ __half g_wqh[(size_t)CH * CH];
__device__ __half g_wph[(size_t)CH * CH];

// ------------------------------ PTX helpers --------------------------------
#define CP16(sa, g) \
    asm volatile("cp.async.cg.shared.global [%0], [%1], 16;" :: "r"(sa), "l"(g))
#define CP_COMMIT() asm volatile("cp.async.commit_group;" ::: "memory")
#define CP_WAIT(n)  asm volatile("cp.async.wait_group %0;" :: "n"(n) : "memory")

__device__ __forceinline__ uint32_t smem_u32(const void* p) {
    uint32_t a;
    asm("{ .reg .u64 t; cvta.to.shared.u64 t, %1; cvt.u32.u64 %0, t; }"
        : "=r"(a) : "l"(p));
    return a;
}

#define MMA_F16(c, a, b) \
    asm volatile("mma.sync.aligned.m16n8k16.row.col.f32.f16.f16.f32 " \
        "{%0,%1,%2,%3}, {%4,%5,%6,%7}, {%8,%9}, {%0,%1,%2,%3};" \
        : "+f"((c)[0]), "+f"((c)[1]), "+f"((c)[2]), "+f"((c)[3]) \
        : "r"((a)[0]), "r"((a)[1]), "r"((a)[2]), "r"((a)[3]), \
          "r"((b)[0]), "r"((b)[1]))

// ------------------------------- small kernels ------------------------------
__global__ void k_zero32(uint32_t* __restrict__ p, size_t n) {
    size_t i = (size_t)blockIdx.x * blockDim.x + threadIdx.x;
    size_t s = (size_t)gridDim.x * blockDim.x;
    for (; i < n; i += s) p[i] = 0u;
}

__global__ void k_cvt(const float* __restrict__ w, __half* __restrict__ h, int n) {
    int i = blockIdx.x * blockDim.x + threadIdx.x;
    if (i < n) h[i] = __float2half(w[i]);
}

// reorg conv weight [O,I,3,3] (fp32) -> [t][O][I] (fp16)
__global__ void k_reorg(const float* __restrict__ w, __half* __restrict__ wt) {
    int g = blockIdx.x * blockDim.x + threadIdx.x;
    #pragma unroll
    for (int t = 0; t < 9; t++)
        wt[(size_t)t * CH * CH + g] = __float2half(w[(size_t)g * 9 + t]);
}

__global__ void k_ln_stats(const float* __restrict__ x) {
    int p = blockIdx.x * blockDim.x + threadIdx.x;
    int b = blockIdx.y;
    const float* xb = x + (size_t)b * CH * HWs + p;
    float s = 0.f, s2 = 0.f;
    #pragma unroll 8
    for (int c = 0; c < CH; c++) {
        float v = xb[(size_t)c * HWs];
        s += v; s2 += v * v;
    }
    float mu = s * (1.f / CH);
    float var = s2 * (1.f / CH) - mu * mu;
    g_mu[b * HWs + p] = mu;
    g_rs[b * HWs + p] = rsqrtf(var + 1e-6f);
}

// LN + transpose to channel-last padded hpT[spo(p)][c] (fp16)
__global__ void k_ln_applyT(const float* __restrict__ x,
                            const float* __restrict__ lw,
                            const float* __restrict__ lb,
                            __half* __restrict__ hpT) {
    __shared__ float t[32][33];
    const int b = blockIdx.z;
    const int c0 = blockIdx.y * 32, p0 = blockIdx.x * 32;
    const int lx = threadIdx.x & 31, ly = threadIdx.x >> 5;
    const int p = p0 + lx;
    const float mu = g_mu[b * HWs + p];
    const float rs = g_rs[b * HWs + p];
    #pragma unroll
    for (int r = 0; r < 32; r += 8) {
        int c = c0 + ly + r;
        float v = x[((size_t)b * CH + c) * HWs + p];
        t[ly + r][lx] = (v - mu) * rs * lw[c] + lb[c];
    }
    __syncthreads();
    #pragma unroll
    for (int r = 0; r < 32; r += 8) {
        int pp = p0 + ly + r;
        int spo = ((pp >> 6) + 1) * PWs + (pp & 63) + 1;
        hpT[((size_t)b * PHWs + spo) * CH + c0 + lx] = __float2half(t[lx][ly + r]);
    }
}

// softmax: fp32 logits row -> fp16 probs row.  Single exp per element.
__global__ void k_softmax(const float* __restrict__ S, __half* __restrict__ P) {
    const int m = blockIdx.x, b = blockIdx.y;
    const float* row = S + ((size_t)b * HWs + m) * HWs;
    __half* prow = P + ((size_t)b * HWs + m) * HWs;
    __shared__ float buf[HWs];
    __shared__ float red[16];
    const int tid = threadIdx.x;
    const int lane = tid & 31, wid = tid >> 5;

    float lmax = -1e30f;
    for (int i = tid; i < HWs; i += 256) {
        float v = row[i];
        buf[i] = v;
        lmax = fmaxf(lmax, v);
    }
    #pragma unroll
    for (int o = 16; o > 0; o >>= 1)
        lmax = fmaxf(lmax, __shfl_xor_sync(0xffffffffu, lmax, o));
    if (lane == 0) red[wid] = lmax;
    __syncthreads();
    float mx = red[0];
    #pragma unroll
    for (int w = 1; w < 8; w++) mx = fmaxf(mx, red[w]);

    float ls = 0.f;
    for (int i = tid; i < HWs; i += 256) {
        float e = __expf(buf[i] - mx);
        buf[i] = e;
        ls += e;
    }
    #pragma unroll
    for (int o = 16; o > 0; o >>= 1)
        ls += __shfl_xor_sync(0xffffffffu, ls, o);
    if (lane == 0) red[8 + wid] = ls;
    __syncthreads();
    float sum = 0.f;
    #pragma unroll
    for (int w = 0; w < 8; w++) sum += red[8 + w];
    const float inv = 1.f / sum;

    for (int i = tid; i < HWs; i += 256)
        prow[i] = __float2half(buf[i] * inv);
}

// ---------------------- unified fp16 mma.sync GEMM --------------------------
// acc[m,n] = sum_k A(m,k)*B(n,k), fp16 operands, fp32 accum.
// mode 0: dense A(lda) / dense B(ldb)
// mode 1: A = hpT gather (1 tap, rows spo(mBase+r)), B dense ldb=CH
// mode 2: A = hpT gather (9 taps, +off(t)),  B = weight slabs (+t*CH*CH)
// mode 3: A = weight slabs (+t*CH*CH),       B = hpT gather (9 taps)
// epiMode 0: float C[m*ldc+n] = alpha*acc (+bias[m]) (+resid[m*ldc+n])
// epiMode 2: half  C[m*ldc+n] = alpha*acc
__global__ void __launch_bounds__(256, 2)
tgemm(const __half* __restrict__ A, const __half* __restrict__ B,
      void* __restrict__ Cv, const float* __restrict__ resid,
      const float* __restrict__ bias,
      int KT, int mode, int lda, int ldb, int ldc,
      size_t sA, size_t sB, size_t sC, float alpha, int epiMode) {
    extern __shared__ char dsm[];
    __half* smh = (__half*)dsm;
    const int tid = threadIdx.x;
    const int lane = tid & 31;
    const int w  = tid >> 5;
    const int wm = (w & 3) * 32;     // warp m offset
    const int wn = (w >> 2) * 64;    // warp n offset
    const int g  = lane >> 2;
    const int t4 = lane & 3;

    const int mBase = blockIdx.y * BM, nBase = blockIdx.x * BN;
    A += blockIdx.z * sA;
    B += blockIdx.z * sB;
    if (resid) resid += blockIdx.z * sC;

    // ---- producer addressing: 2 A chunks + 2 B chunks of 16B per thread ----
    uint32_t aSm[2], bSm[2];
    size_t   aG[2], bG[2];
    int      aSpo[2], bSpo[2], q8[2];
    const uint32_t smBase = smem_u32(dsm);
    #pragma unroll
    for (int i = 0; i < 2; i++) {
        int chunk = tid + 256 * i;
        int r = chunk >> 2;
        q8[i] = (chunk & 3) * 8;
        aSm[i] = (uint32_t)(r * RS + q8[i]) * 2u;
        bSm[i] = (uint32_t)A_BYTES + aSm[i];
        int pa = mBase + r, pb = nBase + r;
        aSpo[i] = ((pa >> 6) + 1) * PWs + (pa & 63) + 1;
        bSpo[i] = ((pb >> 6) + 1) * PWs + (pb & 63) + 1;
        aG[i] = (size_t)pa * lda + q8[i];
        bG[i] = (size_t)pb * ldb + q8[i];
    }

    float acc[2][8][4];
    #pragma unroll
    for (int mt = 0; mt < 2; mt++)
        #pragma unroll
        for (int nt = 0; nt < 8; nt++)
            #pragma unroll
            for (int e = 0; e < 4; e++) acc[mt][nt][e] = 0.f;

    auto issue = [&](int kt) {
        if (kt < KT) {
            const int s = kt % ST;
            const uint32_t sb = smBase + (uint32_t)(s * STAGE_BYTES);
            const int kg = kt * BK;
            if (mode == 0) {
                #pragma unroll
                for (int i = 0; i < 2; i++) {
                    CP16(sb + aSm[i], A + aG[i] + kg);
                    CP16(sb + bSm[i], B + bG[i] + kg);
                }
            } else {
                int t, kc, off;
                if (mode == 1) { t = 0; kc = kg; off = 0; }
                else {
                    t = kg >> 9; kc = kg & 511;
                    off = (t / 3 - 1) * PWs + (t % 3 - 1);
                }
                const __half* Slab = (mode == 3 ? A : B) + ((size_t)t << 18);
                if (mode <= 2) {
                    #pragma unroll
                    for (int i = 0; i < 2; i++) {
                        CP16(sb + aSm[i],
                             A + ((size_t)(aSpo[i] + off) << 9) + kc + q8[i]);
                        CP16(sb + bSm[i], Slab + bG[i] + kc);
                    }
                } else {
                    #pragma unroll
                    for (int i = 0; i < 2; i++) {
                        CP16(sb + aSm[i], Slab + aG[i] + kc);
                        CP16(sb + bSm[i],
                             B + ((size_t)(bSpo[i] + off) << 9) + kc + q8[i]);
                    }
                }
            }
        }
        CP_COMMIT();
    };

    issue(0);
    issue(1);

    for (int kt = 0; kt < KT; kt++) {
        CP_WAIT(1);
        __syncthreads();
        issue(kt + 2);

        const __half* As = smh + (kt % ST) * (STAGE_BYTES / 2);
        const __half* Bs = As + A_HALFS;
        #pragma unroll
        for (int ks = 0; ks < 2; ks++) {
            const int ko = ks * 16;
            uint32_t a[2][4], b[8][2];
            #pragma unroll
            for (int mt = 0; mt < 2; mt++) {
                const int r0 = wm + mt * 16 + g;
                a[mt][0] = *(const uint32_t*)&As[r0 * RS + ko + 2 * t4];
                a[mt][1] = *(const uint32_t*)&As[(r0 + 8) * RS + ko + 2 * t4];
                a[mt][2] = *(const uint32_t*)&As[r0 * RS + ko + 8 + 2 * t4];
                a[mt][3] = *(const uint32_t*)&As[(r0 + 8) * RS + ko + 8 + 2 * t4];
            }
            #pragma unroll
            for (int nt = 0; nt < 8; nt++) {
                const int n0 = wn + nt * 8 + g;
                b[nt][0] = *(const uint32_t*)&Bs[n0 * RS + ko + 2 * t4];
                b[nt][1] = *(const uint32_t*)&Bs[n0 * RS + ko + 8 + 2 * t4];
            }
            #pragma unroll
            for (int mt = 0; mt < 2; mt++)
                #pragma unroll
                for (int nt = 0; nt < 8; nt++)
                    MMA_F16(acc[mt][nt], a[mt], b[nt]);
        }
    }

    // ------------------------------ epilogue --------------------------------
    if (epiMode == 0) {
        float* C = (float*)Cv + blockIdx.z * sC;
        #pragma unroll
        for (int mt = 0; mt < 2; mt++) {
            const int r0 = mBase + wm + mt * 16 + g;
            const int r1 = r0 + 8;
            const float bv0 = bias ? bias[r0] : 0.f;
            const float bv1 = bias ? bias[r1] : 0.f;
            #pragma unroll
            for (int nt = 0; nt < 8; nt++) {
                const int cc = nBase + wn + nt * 8 + 2 * t4;
                float2 o0, o1;
                o0.x = acc[mt][nt][0] * alpha + bv0;
                o0.y = acc[mt][nt][1] * alpha + bv0;
                o1.x = acc[mt][nt][2] * alpha + bv1;
                o1.y = acc[mt][nt][3] * alpha + bv1;
                if (resid) {
                    float2 q0 = *(const float2*)&resid[(size_t)r0 * ldc + cc];
                    float2 q1 = *(const float2*)&resid[(size_t)r1 * ldc + cc];
                    o0.x += q0.x; o0.y += q0.y;
                    o1.x += q1.x; o1.y += q1.y;
                }
                *(float2*)&C[(size_t)r0 * ldc + cc] = o0;
                *(float2*)&C[(size_t)r1 * ldc + cc] = o1;
            }
        }
    } else {
        __half* C = (__half*)Cv + blockIdx.z * sC;
        #pragma unroll
        for (int mt = 0; mt < 2; mt++) {
            const int r0 = mBase + wm + mt * 16 + g;
            const int r1 = r0 + 8;
            #pragma unroll
            for (int nt = 0; nt < 8; nt++) {
                const int cc = nBase + wn + nt * 8 + 2 * t4;
                __half2 h0 = __floats2half2_rn(acc[mt][nt][0] * alpha,
                                               acc[mt][nt][1] * alpha);
                __half2 h1 = __floats2half2_rn(acc[mt][nt][2] * alpha,
                                               acc[mt][nt][3] * alpha);
                *(__half2*)&C[(size_t)r0 * ldc + cc] = h0;
                *(__half2*)&C[(size_t)r1 * ldc + cc] = h1;
            }
        }
    }
}

// ------------------------------- launcher -----------------------------------
extern "C" void kernel_launch(void* const* d_in, const int* in_sizes, int n_in,
                              void* d_out, int out_size) {
    const float* x   = (const float*)d_in[0];
    const float* lnw = (const float*)d_in[1];
    const float* lnb = (const float*)d_in[2];
    const float* wq  = (const float*)d_in[3];
    const float* wk  = (const float*)d_in[4];
    const float* wv  = (const float*)d_in[5];
    const float* wp  = (const float*)d_in[6];
    const float* bp  = (const float*)d_in[7];
    float* out = (float*)d_out;

    __half *p_hpT, *p_qT, *p_kT, *p_v, *p_aoT, *p_P, *p_wkt, *p_wvt, *p_wqh, *p_wph;
    float *p_S;
    cudaGetSymbolAddress((void**)&p_hpT, g_hpT);
    cudaGetSymbolAddress((void**)&p_qT,  g_qT);
    cudaGetSymbolAddress((void**)&p_kT,  g_kT);
    cudaGetSymbolAddress((void**)&p_v,   g_v);
    cudaGetSymbolAddress((void**)&p_aoT, g_aoT);
    cudaGetSymbolAddress((void**)&p_S,   g_S);
    cudaGetSymbolAddress((void**)&p_P,   g_P);
    cudaGetSymbolAddress((void**)&p_wkt, g_wkt);
    cudaGetSymbolAddress((void**)&p_wvt, g_wvt);
    cudaGetSymbolAddress((void**)&p_wqh, g_wqh);
    cudaGetSymbolAddress((void**)&p_wph, g_wph);

    cudaFuncSetAttribute(tgemm, cudaFuncAttributeMaxDynamicSharedMemorySize,
                         SMEM_DYN);

    // LN -> channel-last padded hpT (fp16); weight conversion/reorg
    k_zero32<<<2048, 256>>>((uint32_t*)p_hpT, (size_t)NB * PHWs * CH / 2);
    k_ln_stats<<<dim3(HWs / 256, NB), 256>>>(x);
    k_ln_applyT<<<dim3(HWs / 32, CH / 32, NB), 256>>>(x, lnw, lnb, p_hpT);
    k_reorg<<<CH * CH / 256, 256>>>(wk, p_wkt);
    k_reorg<<<CH * CH / 256, 256>>>(wv, p_wvt);
    k_cvt<<<CH * CH / 256, 256>>>(wq, p_wqh, CH * CH);
    k_cvt<<<CH * CH / 256, 256>>>(wp, p_wph, CH * CH);

    const size_t sHP = (size_t)PHWs * CH;
    const size_t sPC = (size_t)HWs * CH;
    const size_t sSS = (size_t)HWs * HWs;

    // qT[p][c]: M=p (A = hpT gather 1 tap), N=o (B = wq)
    tgemm<<<dim3(4, 32, NB), 256, SMEM_DYN>>>(
        p_hpT, p_wqh, p_qT, nullptr, nullptr,
        16, 1, CH, CH, CH, sHP, 0, sPC, 1.f, 2);
    // kT[p][c]: M=p (A = hpT gather 9 taps), N=o (B = wkt slabs)
    tgemm<<<dim3(4, 32, NB), 256, SMEM_DYN>>>(
        p_hpT, p_wkt, p_kT, nullptr, nullptr,
        144, 2, CH, CH, CH, sHP, 0, sPC, 1.f, 2);
    // v[c][p]: M=o (A = wvt slabs), N=p (B = hpT gather 9 taps)
    tgemm<<<dim3(32, 4, NB), 256, SMEM_DYN>>>(
        p_wvt, p_hpT, p_v, nullptr, nullptr,
        144, 3, CH, CH, HWs, 0, sHP, sPC, 1.f, 2);

    // S[m,n] = scale * sum_c qT[m,c] kT[n,c]  (fp32 logits)
    const float scale = 0.044194173824159216f;  // 512^-0.5
    tgemm<<<dim3(32, 32, NB), 256, SMEM_DYN>>>(
        p_qT, p_kT, p_S, nullptr, nullptr,
        16, 0, CH, CH, HWs, sPC, sPC, sSS, scale, 0);

    // softmax rows: fp32 logits -> fp16 probs (single exp)
    k_softmax<<<dim3(HWs, NB), 256>>>(p_S, p_P);

    // aoT[p][c]: M=p (A = P row-major), N=c (B = v [c][n])
    tgemm<<<dim3(4, 32, NB), 256, SMEM_DYN>>>(
        p_P, p_v, p_aoT, nullptr, nullptr,
        128, 0, HWs, HWs, CH, sSS, sPC, sPC, 1.f, 2);

    // out[o,p] = x + wp*aoT + bp  (fp32)
    tgemm<<<dim3(32, 4, NB), 256, SMEM_DYN>>>(
        p_wph, p_aoT, out, x, bp,
        16, 0, CH, CH, HWs, 0, sPC, sPC, 1.f, 0);
}

// round 6
// speedup vs baseline: 5.6649x; 1.1456x over previous
#include <cuda_runtime.h>
#include <cuda_fp16.h>
#include <cstdint>

// ===========================================================================
// AttnBlock via mma.sync m16n8k16 fp16 (fp32 accum), sm_100-safe.
// Round 6: fused q/k/v conv launch (job-decoded blocks), FMA-poly exp in
// softmax, merged weight prep, border-only zero.  Launch order puts the
// fused QKV GEMM at ncu's capture slot (#5).
// ===========================================================================

namespace {
constexpr int CH   = 512;
constexpr int NB   = 4;
constexpr int HWs  = 4096;
constexpr int PWs  = 66;
constexpr int PHWs = PWs * PWs;   // 4356

constexpr int BM = 128, BN = 128, BK = 32, ST = 3;
constexpr int RS = 40;                           // padded row stride (halfs)
constexpr int A_HALFS = BM * RS;                 // 5120
constexpr int A_BYTES = A_HALFS * 2;             // 10240
constexpr int STAGE_BYTES = 2 * A_BYTES;         // 20480
constexpr int SMEM_DYN = ST * STAGE_BYTES;       // 61440
}

// ------------------------- scratch (device globals) ------------------------
__device__ float  g_mu [NB * HWs];
__device__ float  g_rs [NB * HWs];
__device__ __half g_hpT[(size_t)NB * PHWs * CH];   // padded LN out, channel-last
__device__ __half g_qT [(size_t)NB * HWs * CH];    // [p][c]
__device__ __half g_kT [(size_t)NB * HWs * CH];    // [p][c]
__device__ __half g_v  [(size_t)NB * CH * HWs];    // [c][p]
__device__ __half g_aoT[(size_t)NB * HWs * CH];    // [p][c]
__device__ float  g_S  [(size_t)NB * HWs * HWs];   // fp32 logits
__device__ __half g_P  [(size_t)NB * HWs * HWs];   // fp16 probs
__device__ __half g_wkt[(size_t)9 * CH * CH];      // [t][o][i] fp16
__device__ __half g_wvt[(size_t)9 * CH * CH];
__device__ __half g_wqh[(size_t)CH * CH];
__device__ __half g_wph[(size_t)CH * CH];

// ------------------------------ PTX helpers --------------------------------
#define CP16(sa, g) \
    asm volatile("cp.async.cg.shared.global [%0], [%1], 16;" :: "r"(sa), "l"(g))
#define CP_COMMIT() asm volatile("cp.async.commit_group;" ::: "memory")
#define CP_WAIT(n)  asm volatile("cp.async.wait_group %0;" :: "n"(n) : "memory")

__device__ __forceinline__ uint32_t smem_u32(const void* p) {
    uint32_t a;
    asm("{ .reg .u64 t; cvta.to.shared.u64 t, %1; cvt.u32.u64 %0, t; }"
        : "=r"(a) : "l"(p));
    return a;
}

#define MMA_F16(c, a, b) \
    asm volatile("mma.sync.aligned.m16n8k16.row.col.f32.f16.f16.f32 " \
        "{%0,%1,%2,%3}, {%4,%5,%6,%7}, {%8,%9}, {%0,%1,%2,%3};" \
        : "+f"((c)[0]), "+f"((c)[1]), "+f"((c)[2]), "+f"((c)[3]) \
        : "r"((a)[0]), "r"((a)[1]), "r"((a)[2]), "r"((a)[3]), \
          "r"((b)[0]), "r"((b)[1]))

// FMA-pipe exp (no MUFU): exp(x) = 2^n * e^t, |t| <= ln2/2.  rel err ~2.4e-6.
__device__ __forceinline__ float fexp(float x) {
    x = fmaxf(x, -80.f);
    float y  = x * 1.4426950408889634f;
    float fn = rintf(y);
    float t  = (y - fn) * 0.6931471805599453f;
    float p  = 8.3333333e-3f;                 // 1/120
    p = fmaf(p, t, 4.1666667e-2f);            // 1/24
    p = fmaf(p, t, 1.6666667e-1f);            // 1/6
    p = fmaf(p, t, 0.5f);
    p = fmaf(p, t, 1.f);
    p = fmaf(p, t, 1.f);
    return p * __int_as_float(((int)fn + 127) << 23);
}

// ------------------------------- small kernels ------------------------------
// all weight prep in one kernel: wq/wp fp32->fp16, wk/wv reorg [O,I,3,3]->[t][O][I]
__global__ void k_prep(const float* __restrict__ wq, const float* __restrict__ wk,
                       const float* __restrict__ wv, const float* __restrict__ wp) {
    int g = blockIdx.x * blockDim.x + threadIdx.x;  // 0..CH*CH-1
    g_wqh[g] = __float2half(wq[g]);
    g_wph[g] = __float2half(wp[g]);
    #pragma unroll
    for (int t = 0; t < 9; t++) {
        g_wkt[(size_t)t * CH * CH + g] = __float2half(wk[(size_t)g * 9 + t]);
        g_wvt[(size_t)t * CH * CH + g] = __float2half(wv[(size_t)g * 9 + t]);
    }
}

// zero only the padded border of g_hpT (interior rewritten every call)
__global__ void k_border() {
    const int i = blockIdx.x;            // 0..259 border positions
    const int b = blockIdx.y;
    int spo;
    if (i < 66)       spo = i;                       // row 0
    else if (i < 132) spo = 65 * PWs + (i - 66);     // row 65
    else if (i < 196) spo = (i - 131) * PWs;         // col 0, rows 1..64
    else              spo = (i - 195) * PWs + 65;    // col 65, rows 1..64
    uint32_t* row = (uint32_t*)&g_hpT[((size_t)b * PHWs + spo) * CH];
    row[threadIdx.x] = 0u;               // 256 threads x 4B = 512 halfs
}

__global__ void k_ln_stats(const float* __restrict__ x) {
    int p = blockIdx.x * blockDim.x + threadIdx.x;
    int b = blockIdx.y;
    const float* xb = x + (size_t)b * CH * HWs + p;
    float s = 0.f, s2 = 0.f;
    #pragma unroll 8
    for (int c = 0; c < CH; c++) {
        float v = xb[(size_t)c * HWs];
        s += v; s2 += v * v;
    }
    float mu = s * (1.f / CH);
    float var = s2 * (1.f / CH) - mu * mu;
    g_mu[b * HWs + p] = mu;
    g_rs[b * HWs + p] = rsqrtf(var + 1e-6f);
}

// LN + transpose to channel-last padded hpT[spo(p)][c] (fp16)
__global__ void k_ln_applyT(const float* __restrict__ x,
                            const float* __restrict__ lw,
                            const float* __restrict__ lb) {
    __shared__ float t[32][33];
    const int b = blockIdx.z;
    const int c0 = blockIdx.y * 32, p0 = blockIdx.x * 32;
    const int lx = threadIdx.x & 31, ly = threadIdx.x >> 5;
    const int p = p0 + lx;
    const float mu = g_mu[b * HWs + p];
    const float rs = g_rs[b * HWs + p];
    #pragma unroll
    for (int r = 0; r < 32; r += 8) {
        int c = c0 + ly + r;
        float v = x[((size_t)b * CH + c) * HWs + p];
        t[ly + r][lx] = (v - mu) * rs * lw[c] + lb[c];
    }
    __syncthreads();
    #pragma unroll
    for (int r = 0; r < 32; r += 8) {
        int pp = p0 + ly + r;
        int spo = ((pp >> 6) + 1) * PWs + (pp & 63) + 1;
        g_hpT[((size_t)b * PHWs + spo) * CH + c0 + lx] = __float2half(t[lx][ly + r]);
    }
}

// softmax: fp32 logits row -> fp16 probs row.  Single FMA-poly exp / element.
__global__ void k_softmax(const float* __restrict__ S, __half* __restrict__ P) {
    const int m = blockIdx.x, b = blockIdx.y;
    const float* row = S + ((size_t)b * HWs + m) * HWs;
    __half* prow = P + ((size_t)b * HWs + m) * HWs;
    __shared__ float buf[HWs];
    __shared__ float red[16];
    const int tid = threadIdx.x;
    const int lane = tid & 31, wid = tid >> 5;

    float lmax = -1e30f;
    #pragma unroll
    for (int it = 0; it < 4; it++) {
        int i = tid * 4 + it * 1024;
        float4 v = *(const float4*)&row[i];
        *(float4*)&buf[i] = v;
        lmax = fmaxf(fmaxf(fmaxf(lmax, v.x), fmaxf(v.y, v.z)), v.w);
    }
    #pragma unroll
    for (int o = 16; o > 0; o >>= 1)
        lmax = fmaxf(lmax, __shfl_xor_sync(0xffffffffu, lmax, o));
    if (lane == 0) red[wid] = lmax;
    __syncthreads();
    float mx = red[0];
    #pragma unroll
    for (int w = 1; w < 8; w++) mx = fmaxf(mx, red[w]);

    float ls = 0.f;
    #pragma unroll
    for (int it = 0; it < 4; it++) {
        int i = tid * 4 + it * 1024;
        float4 v = *(float4*)&buf[i];
        v.x = fexp(v.x - mx); v.y = fexp(v.y - mx);
        v.z = fexp(v.z - mx); v.w = fexp(v.w - mx);
        *(float4*)&buf[i] = v;
        ls += (v.x + v.y) + (v.z + v.w);
    }
    #pragma unroll
    for (int o = 16; o > 0; o >>= 1)
        ls += __shfl_xor_sync(0xffffffffu, ls, o);
    if (lane == 0) red[8 + wid] = ls;
    __syncthreads();
    float sum = 0.f;
    #pragma unroll
    for (int w = 0; w < 8; w++) sum += red[8 + w];
    const float inv = 1.f / sum;

    #pragma unroll
    for (int it = 0; it < 4; it++) {
        int i = tid * 4 + it * 1024;
        float4 v = *(float4*)&buf[i];
        __half2 h0 = __floats2half2_rn(v.x * inv, v.y * inv);
        __half2 h1 = __floats2half2_rn(v.z * inv, v.w * inv);
        *(__half2*)&prow[i]     = h0;
        *(__half2*)&prow[i + 2] = h1;
    }
}

// ---------------------- fp16 mma.sync GEMM core -----------------------------
// acc[m,n] = sum_k A(m,k)*B(n,k), fp16 operands, fp32 accum.
// mode 0: dense A(lda) / dense B(ldb)
// mode 1: A = hpT gather (1 tap), B dense
// mode 2: A = hpT gather (9 taps), B = weight slabs (+t*CH*CH)
// mode 3: A = weight slabs,        B = hpT gather (9 taps)
// epiMode 0: float C[m*ldc+n] = alpha*acc (+bias[m]) (+resid[m*ldc+n])
// epiMode 2: half  C[m*ldc+n] = alpha*acc
__device__ __forceinline__ void gemm_core(
    const __half* __restrict__ A, const __half* __restrict__ B,
    void* __restrict__ Cv, const float* __restrict__ resid,
    const float* __restrict__ bias,
    int KT, int mode, int lda, int ldb, int ldc,
    float alpha, int epiMode, int mBase, int nBase) {
    extern __shared__ char dsm[];
    __half* smh = (__half*)dsm;
    const int tid = threadIdx.x;
    const int lane = tid & 31;
    const int w  = tid >> 5;
    const int wm = (w & 3) * 32;
    const int wn = (w >> 2) * 64;
    const int g  = lane >> 2;
    const int t4 = lane & 3;

    uint32_t aSm[2], bSm[2];
    size_t   aG[2], bG[2];
    int      aSpo[2], bSpo[2], q8[2];
    const uint32_t smBase = smem_u32(dsm);
    #pragma unroll
    for (int i = 0; i < 2; i++) {
        int chunk = tid + 256 * i;
        int r = chunk >> 2;
        q8[i] = (chunk & 3) * 8;
        aSm[i] = (uint32_t)(r * RS + q8[i]) * 2u;
        bSm[i] = (uint32_t)A_BYTES + aSm[i];
        int pa = mBase + r, pb = nBase + r;
        aSpo[i] = ((pa >> 6) + 1) * PWs + (pa & 63) + 1;
        bSpo[i] = ((pb >> 6) + 1) * PWs + (pb & 63) + 1;
        aG[i] = (size_t)pa * lda + q8[i];
        bG[i] = (size_t)pb * ldb + q8[i];
    }

    float acc[2][8][4];
    #pragma unroll
    for (int mt = 0; mt < 2; mt++)
        #pragma unroll
        for (int nt = 0; nt < 8; nt++)
            #pragma unroll
            for (int e = 0; e < 4; e++) acc[mt][nt][e] = 0.f;

    auto issue = [&](int kt) {
        if (kt < KT) {
            const int s = kt % ST;
            const uint32_t sb = smBase + (uint32_t)(s * STAGE_BYTES);
            const int kg = kt * BK;
            if (mode == 0) {
                #pragma unroll
                for (int i = 0; i < 2; i++) {
                    CP16(sb + aSm[i], A + aG[i] + kg);
                    CP16(sb + bSm[i], B + bG[i] + kg);
                }
            } else {
                int t, kc, off;
                if (mode == 1) { t = 0; kc = kg; off = 0; }
                else {
                    t = kg >> 9; kc = kg & 511;
                    off = (t / 3 - 1) * PWs + (t % 3 - 1);
                }
                const __half* Slab = (mode == 3 ? A : B) + ((size_t)t << 18);
                if (mode <= 2) {
                    #pragma unroll
                    for (int i = 0; i < 2; i++) {
                        CP16(sb + aSm[i],
                             A + ((size_t)(aSpo[i] + off) << 9) + kc + q8[i]);
                        CP16(sb + bSm[i], Slab + bG[i] + kc);
                    }
                } else {
                    #pragma unroll
                    for (int i = 0; i < 2; i++) {
                        CP16(sb + aSm[i], Slab + aG[i] + kc);
                        CP16(sb + bSm[i],
                             B + ((size_t)(bSpo[i] + off) << 9) + kc + q8[i]);
                    }
                }
            }
        }
        CP_COMMIT();
    };

    issue(0);
    issue(1);

    for (int kt = 0; kt < KT; kt++) {
        CP_WAIT(1);
        __syncthreads();
        issue(kt + 2);

        const __half* As = smh + (kt % ST) * (STAGE_BYTES / 2);
        const __half* Bs = As + A_HALFS;
        #pragma unroll
        for (int ks = 0; ks < 2; ks++) {
            const int ko = ks * 16;
            uint32_t a[2][4], b[8][2];
            #pragma unroll
            for (int mt = 0; mt < 2; mt++) {
                const int r0 = wm + mt * 16 + g;
                a[mt][0] = *(const uint32_t*)&As[r0 * RS + ko + 2 * t4];
                a[mt][1] = *(const uint32_t*)&As[(r0 + 8) * RS + ko + 2 * t4];
                a[mt][2] = *(const uint32_t*)&As[r0 * RS + ko + 8 + 2 * t4];
                a[mt][3] = *(const uint32_t*)&As[(r0 + 8) * RS + ko + 8 + 2 * t4];
            }
            #pragma unroll
            for (int nt = 0; nt < 8; nt++) {
                const int n0 = wn + nt * 8 + g;
                b[nt][0] = *(const uint32_t*)&Bs[n0 * RS + ko + 2 * t4];
                b[nt][1] = *(const uint32_t*)&Bs[n0 * RS + ko + 8 + 2 * t4];
            }
            #pragma unroll
            for (int mt = 0; mt < 2; mt++)
                #pragma unroll
                for (int nt = 0; nt < 8; nt++)
                    MMA_F16(acc[mt][nt], a[mt], b[nt]);
        }
    }

    if (epiMode == 0) {
        float* C = (float*)Cv;
        #pragma unroll
        for (int mt = 0; mt < 2; mt++) {
            const int r0 = mBase + wm + mt * 16 + g;
            const int r1 = r0 + 8;
            const float bv0 = bias ? bias[r0] : 0.f;
            const float bv1 = bias ? bias[r1] : 0.f;
            #pragma unroll
            for (int nt = 0; nt < 8; nt++) {
                const int cc = nBase + wn + nt * 8 + 2 * t4;
                float2 o0, o1;
                o0.x = acc[mt][nt][0] * alpha + bv0;
                o0.y = acc[mt][nt][1] * alpha + bv0;
                o1.x = acc[mt][nt][2] * alpha + bv1;
                o1.y = acc[mt][nt][3] * alpha + bv1;
                if (resid) {
                    float2 q0 = *(const float2*)&resid[(size_t)r0 * ldc + cc];
                    float2 q1 = *(const float2*)&resid[(size_t)r1 * ldc + cc];
                    o0.x += q0.x; o0.y += q0.y;
                    o1.x += q1.x; o1.y += q1.y;
                }
                *(float2*)&C[(size_t)r0 * ldc + cc] = o0;
                *(float2*)&C[(size_t)r1 * ldc + cc] = o1;
            }
        }
    } else {
        __half* C = (__half*)Cv;
        #pragma unroll
        for (int mt = 0; mt < 2; mt++) {
            const int r0 = mBase + wm + mt * 16 + g;
            const int r1 = r0 + 8;
            #pragma unroll
            for (int nt = 0; nt < 8; nt++) {
                const int cc = nBase + wn + nt * 8 + 2 * t4;
                __half2 h0 = __floats2half2_rn(acc[mt][nt][0] * alpha,
                                               acc[mt][nt][1] * alpha);
                __half2 h1 = __floats2half2_rn(acc[mt][nt][2] * alpha,
                                               acc[mt][nt][3] * alpha);
                *(__half2*)&C[(size_t)r0 * ldc + cc] = h0;
                *(__half2*)&C[(size_t)r1 * ldc + cc] = h1;
            }
        }
    }
}

// generic GEMM wrapper (S, O, proj)
__global__ void __launch_bounds__(256, 2)
tgemm(const __half* __restrict__ A, const __half* __restrict__ B,
      void* __restrict__ Cv, const float* __restrict__ resid,
      const float* __restrict__ bias,
      int KT, int mode, int lda, int ldb, int ldc,
      size_t sA, size_t sB, size_t sC, float alpha, int epiMode) {
    const int z = blockIdx.z;
    gemm_core(A + z * sA, B + z * sB,
              epiMode ? (void*)((__half*)Cv + z * sC) : (void*)((float*)Cv + z * sC),
              resid ? resid + z * sC : nullptr, bias,
              KT, mode, lda, ldb, ldc, alpha, epiMode,
              blockIdx.y * BM, blockIdx.x * BN);
}

// fused q/k/v conv launch: 384 blocks per batch, job decoded from blockIdx.x
__global__ void __launch_bounds__(256, 2)
qkv_gemm() {
    const int z = blockIdx.z;
    const size_t sHP = (size_t)PHWs * CH;
    const size_t sPC = (size_t)HWs * CH;
    const __half* hp = g_hpT + z * sHP;
    const int bx = blockIdx.x;
    if (bx < 128) {            // q: M=p, N=c, 1 tap
        gemm_core(hp, g_wqh, g_qT + z * sPC, nullptr, nullptr,
                  16, 1, CH, CH, CH, 1.f, 2, (bx >> 2) * BM, (bx & 3) * BN);
    } else if (bx < 256) {     // k: M=p, N=c, 9 taps
        const int j = bx - 128;
        gemm_core(hp, g_wkt, g_kT + z * sPC, nullptr, nullptr,
                  144, 2, CH, CH, CH, 1.f, 2, (j >> 2) * BM, (j & 3) * BN);
    } else {                   // v: M=c, N=p, 9 taps
        const int j = bx - 256;
        gemm_core(g_wvt, hp, g_v + z * sPC, nullptr, nullptr,
                  144, 3, CH, CH, HWs, 1.f, 2, (j >> 5) * BM, (j & 31) * BN);
    }
}

// ------------------------------- launcher -----------------------------------
extern "C" void kernel_launch(void* const* d_in, const int* in_sizes, int n_in,
                              void* d_out, int out_size) {
    const float* x   = (const float*)d_in[0];
    const float* lnw = (const float*)d_in[1];
    const float* lnb = (const float*)d_in[2];
    const float* wq  = (const float*)d_in[3];
    const float* wk  = (const float*)d_in[4];
    const float* wv  = (const float*)d_in[5];
    const float* wp  = (const float*)d_in[6];
    const float* bp  = (const float*)d_in[7];
    float* out = (float*)d_out;

    __half *p_qT, *p_kT, *p_v, *p_aoT, *p_P, *p_wph;
    float *p_S;
    cudaGetSymbolAddress((void**)&p_qT,  g_qT);
    cudaGetSymbolAddress((void**)&p_kT,  g_kT);
    cudaGetSymbolAddress((void**)&p_v,   g_v);
    cudaGetSymbolAddress((void**)&p_aoT, g_aoT);
    cudaGetSymbolAddress((void**)&p_S,   g_S);
    cudaGetSymbolAddress((void**)&p_P,   g_P);
    cudaGetSymbolAddress((void**)&p_wph, g_wph);

    cudaFuncSetAttribute(tgemm, cudaFuncAttributeMaxDynamicSharedMemorySize,
                         SMEM_DYN);
    cudaFuncSetAttribute(qkv_gemm, cudaFuncAttributeMaxDynamicSharedMemorySize,
                         SMEM_DYN);

    const size_t sPC = (size_t)HWs * CH;
    const size_t sSS = (size_t)HWs * HWs;

    // 1..4: prep
    k_ln_stats<<<dim3(HWs / 256, NB), 256>>>(x);
    k_prep<<<CH * CH / 256, 256>>>(wq, wk, wv, wp);
    k_ln_applyT<<<dim3(HWs / 32, CH / 32, NB), 256>>>(x, lnw, lnb);
    k_border<<<dim3(260, NB), 256>>>();

    // 5: fused q/k/v convs  (ncu capture slot)
    qkv_gemm<<<dim3(384, 1, NB), 256, SMEM_DYN>>>();

    // 6: S[m,n] = scale * sum_c qT[m,c] kT[n,c]  (fp32 logits)
    const float scale = 0.044194173824159216f;  // 512^-0.5
    tgemm<<<dim3(32, 32, NB), 256, SMEM_DYN>>>(
        p_qT, p_kT, p_S, nullptr, nullptr,
        16, 0, CH, CH, HWs, sPC, sPC, sSS, scale, 0);

    // 7: softmax rows: fp32 logits -> fp16 probs (FMA-poly exp)
    k_softmax<<<dim3(HWs, NB), 256>>>(p_S, p_P);

    // 8: aoT[p][c]: M=p (A = P row-major), N=c (B = v [c][n])
    tgemm<<<dim3(4, 32, NB), 256, SMEM_DYN>>>(
        p_P, p_v, p_aoT, nullptr, nullptr,
        128, 0, HWs, HWs, CH, sSS, sPC, sPC, 1.f, 2);

    // 9: out[o,p] = x + wp*aoT + bp  (fp32)
    tgemm<<<dim3(32, 4, NB), 256, SMEM_DYN>>>(
        p_wph, p_aoT, out, x, bp,
        16, 0, CH, CH, HWs, 0, sPC, sPC, 1.f, 0);
}